// round 1
// baseline (speedup 1.0000x reference)
#include <cuda_runtime.h>
#include <math.h>

#define BB 2
#define SS 2048
#define HH 2048
#define NHH 16
#define HDD 128
#define FFD 8192
#define MTOK (BB*SS)   // 4096

// ---------------- scratch (device globals; no allocations allowed) ----------
__device__ float g_xn[MTOK*HH];
__device__ float g_q [MTOK*HH];
__device__ float g_k [MTOK*HH];
__device__ float g_v [MTOK*HH];
__device__ float g_at[MTOK*HH];
__device__ float g_h [MTOK*HH];
__device__ float g_hn[MTOK*HH];
__device__ float g_ff[MTOK*FFD];

// ---------------- LayerNorm: one block per row, H=2048 ----------------------
__global__ __launch_bounds__(256) void ln_kernel(const float* __restrict__ x,
                                                 const float* __restrict__ g,
                                                 const float* __restrict__ b,
                                                 float* __restrict__ y)
{
    const int row = blockIdx.x;
    const int t   = threadIdx.x;
    const float4* xr = (const float4*)(x + (size_t)row * HH);

    float4 v0 = xr[t];
    float4 v1 = xr[t + 256];

    float s  = v0.x + v0.y + v0.z + v0.w + v1.x + v1.y + v1.z + v1.w;
    float s2 = v0.x*v0.x + v0.y*v0.y + v0.z*v0.z + v0.w*v0.w
             + v1.x*v1.x + v1.y*v1.y + v1.z*v1.z + v1.w*v1.w;

    __shared__ float rs[8], rs2[8];
    #pragma unroll
    for (int o = 16; o >= 1; o >>= 1) {
        s  += __shfl_xor_sync(0xffffffffu, s,  o);
        s2 += __shfl_xor_sync(0xffffffffu, s2, o);
    }
    int wid = t >> 5, lid = t & 31;
    if (lid == 0) { rs[wid] = s; rs2[wid] = s2; }
    __syncthreads();
    if (t == 0) {
        float a = 0.f, a2 = 0.f;
        #pragma unroll
        for (int w = 0; w < 8; w++) { a += rs[w]; a2 += rs2[w]; }
        rs[0] = a; rs2[0] = a2;
    }
    __syncthreads();
    float mu  = rs[0]  * (1.0f / HH);
    float var = rs2[0] * (1.0f / HH) - mu * mu;
    float rstd = rsqrtf(var + 1e-5f);

    const float4* g4 = (const float4*)g;
    const float4* b4 = (const float4*)b;
    float4* y4 = (float4*)(y + (size_t)row * HH);

    float4 gg = g4[t],  bb = b4[t];
    float4 o0;
    o0.x = (v0.x - mu) * rstd * gg.x + bb.x;
    o0.y = (v0.y - mu) * rstd * gg.y + bb.y;
    o0.z = (v0.z - mu) * rstd * gg.z + bb.z;
    o0.w = (v0.w - mu) * rstd * gg.w + bb.w;
    y4[t] = o0;

    gg = g4[t + 256]; bb = b4[t + 256];
    float4 o1;
    o1.x = (v1.x - mu) * rstd * gg.x + bb.x;
    o1.y = (v1.y - mu) * rstd * gg.y + bb.y;
    o1.z = (v1.z - mu) * rstd * gg.z + bb.z;
    o1.w = (v1.w - mu) * rstd * gg.w + bb.w;
    y4[t + 256] = o1;
}

// ---------------- fp32 SGEMM 128x128x8, 8x8 per thread ----------------------
// C[M,N] = op(A[M,K] @ B[K,N])  row-major. EPI: 0 none, 1 +R, 2 gelu
__device__ __forceinline__ float gelu_tanh(float v) {
    float c = 0.7978845608028654f * (v + 0.044715f * v * v * v);
    return 0.5f * v * (1.0f + tanhf(c));
}

template<int EPI>
__global__ __launch_bounds__(256) void sgemm(const float* __restrict__ A,
                                             const float* __restrict__ Bm,
                                             const float* __restrict__ R,
                                             float* __restrict__ C,
                                             int M, int N, int K)
{
    __shared__ float As[8][128];
    __shared__ float Bs[8][128];

    const int n0 = blockIdx.x * 128;
    const int m0 = blockIdx.y * 128;
    const int t  = threadIdx.x;
    const int txc = t & 15, tyc = t >> 4;

    float acc[8][8];
    #pragma unroll
    for (int i = 0; i < 8; i++)
        #pragma unroll
        for (int j = 0; j < 8; j++) acc[i][j] = 0.f;

    const int ar = t >> 1,  ac = (t & 1) * 4;
    const int br = t >> 5,  bc = (t & 31) * 4;
    const float* Aptr = A  + (size_t)(m0 + ar) * K + ac;
    const float* Bptr = Bm + (size_t)br * N + n0 + bc;

    for (int k0 = 0; k0 < K; k0 += 8) {
        float4 av = *(const float4*)(Aptr + k0);
        float4 bv = *(const float4*)(Bptr + (size_t)k0 * N);
        As[ac + 0][ar] = av.x;
        As[ac + 1][ar] = av.y;
        As[ac + 2][ar] = av.z;
        As[ac + 3][ar] = av.w;
        *(float4*)&Bs[br][bc] = bv;
        __syncthreads();

        #pragma unroll
        for (int kk = 0; kk < 8; kk++) {
            float a_[8], b_[8];
            *(float4*)&a_[0] = *(const float4*)&As[kk][tyc * 8];
            *(float4*)&a_[4] = *(const float4*)&As[kk][tyc * 8 + 4];
            *(float4*)&b_[0] = *(const float4*)&Bs[kk][txc * 8];
            *(float4*)&b_[4] = *(const float4*)&Bs[kk][txc * 8 + 4];
            #pragma unroll
            for (int i = 0; i < 8; i++)
                #pragma unroll
                for (int j = 0; j < 8; j++)
                    acc[i][j] = fmaf(a_[i], b_[j], acc[i][j]);
        }
        __syncthreads();
    }

    #pragma unroll
    for (int i = 0; i < 8; i++) {
        size_t off = (size_t)(m0 + tyc * 8 + i) * N + n0 + txc * 8;
        float o[8];
        #pragma unroll
        for (int j = 0; j < 8; j++) o[j] = acc[i][j];
        if (EPI == 1) {
            float4 r0 = *(const float4*)(R + off);
            float4 r1 = *(const float4*)(R + off + 4);
            o[0] += r0.x; o[1] += r0.y; o[2] += r0.z; o[3] += r0.w;
            o[4] += r1.x; o[5] += r1.y; o[6] += r1.z; o[7] += r1.w;
        } else if (EPI == 2) {
            #pragma unroll
            for (int j = 0; j < 8; j++) o[j] = gelu_tanh(o[j]);
        }
        *(float4*)(C + off)     = make_float4(o[0], o[1], o[2], o[3]);
        *(float4*)(C + off + 4) = make_float4(o[4], o[5], o[6], o[7]);
    }
}

// ---------------- Flash attention: 64-query tiles, HD=128, causal -----------
// q,k,v,out layout: [B, S, NH, HD] flattened => ((b*S+s)*H + h*HD + d)
#define FL_SMEM ((3*128*64 + 64*68) * 4)

__global__ __launch_bounds__(256) void flash_kernel(const float* __restrict__ q,
                                                    const float* __restrict__ k,
                                                    const float* __restrict__ v,
                                                    float* __restrict__ o)
{
    extern __shared__ float sm[];
    float* Qt = sm;                 // [128][64]  transposed
    float* Kt = sm + 128 * 64;      // [128][64]  transposed
    float* Vs = sm + 2 * 128 * 64;  // [64][128]
    float* Pt = sm + 3 * 128 * 64;  // [64][68]   transposed probs
    const int PSTR = 68;

    const int qb = blockIdx.x;
    const int bh = blockIdx.y;
    const int bb = bh >> 4, hh = bh & 15;
    const int q0 = qb * 64;
    const int t  = threadIdx.x;
    const int tx = t & 15, ty = t >> 4;
    const float scale = 0.08838834764831845f;  // 128^-0.5

    // load Q (scaled) transposed
    {
        int row = t >> 2;
        int dbase = (t & 3) * 32;
        const float* src = q + ((size_t)(bb * SS + q0 + row) * HH) + hh * HDD + dbase;
        #pragma unroll
        for (int u = 0; u < 8; u++) {
            float4 val = *(const float4*)(src + u * 4);
            int d = dbase + u * 4;
            Qt[(d + 0) * 64 + row] = val.x * scale;
            Qt[(d + 1) * 64 + row] = val.y * scale;
            Qt[(d + 2) * 64 + row] = val.z * scale;
            Qt[(d + 3) * 64 + row] = val.w * scale;
        }
    }

    float m[4], l[4], acc[4][8];
    #pragma unroll
    for (int i = 0; i < 4; i++) {
        m[i] = -1e30f; l[i] = 0.f;
        #pragma unroll
        for (int c = 0; c < 8; c++) acc[i][c] = 0.f;
    }

    for (int kt = 0; kt <= qb; kt++) {
        const int k0 = kt * 64;
        __syncthreads();  // previous PV / Q stores done before K,V overwrite
        {
            int row = t >> 2;
            int dbase = (t & 3) * 32;
            const float* ksrc = k + ((size_t)(bb * SS + k0 + row) * HH) + hh * HDD + dbase;
            const float* vsrc = v + ((size_t)(bb * SS + k0 + row) * HH) + hh * HDD + dbase;
            #pragma unroll
            for (int u = 0; u < 8; u++) {
                int d = dbase + u * 4;
                float4 kvv = *(const float4*)(ksrc + u * 4);
                Kt[(d + 0) * 64 + row] = kvv.x;
                Kt[(d + 1) * 64 + row] = kvv.y;
                Kt[(d + 2) * 64 + row] = kvv.z;
                Kt[(d + 3) * 64 + row] = kvv.w;
                *(float4*)&Vs[row * 128 + d] = *(const float4*)(vsrc + u * 4);
            }
        }
        __syncthreads();

        // S = Q K^T  (4x4 per thread)
        float s[4][4];
        #pragma unroll
        for (int i = 0; i < 4; i++)
            #pragma unroll
            for (int j = 0; j < 4; j++) s[i][j] = 0.f;

        #pragma unroll 4
        for (int d = 0; d < 128; d++) {
            float a_[4], b_[4];
            *(float4*)a_ = *(const float4*)&Qt[d * 64 + ty * 4];
            *(float4*)b_ = *(const float4*)&Kt[d * 64 + tx * 4];
            #pragma unroll
            for (int i = 0; i < 4; i++)
                #pragma unroll
                for (int j = 0; j < 4; j++)
                    s[i][j] = fmaf(a_[i], b_[j], s[i][j]);
        }

        if (kt == qb) {  // diagonal tile: causal mask
            #pragma unroll
            for (int i = 0; i < 4; i++)
                #pragma unroll
                for (int j = 0; j < 4; j++)
                    if (k0 + tx * 4 + j > q0 + ty * 4 + i) s[i][j] = -1e30f;
        }

        // online softmax per row (rows shared across the 16 tx lanes)
        #pragma unroll
        for (int i = 0; i < 4; i++) {
            float mt = fmaxf(fmaxf(s[i][0], s[i][1]), fmaxf(s[i][2], s[i][3]));
            #pragma unroll
            for (int off = 8; off >= 1; off >>= 1)
                mt = fmaxf(mt, __shfl_xor_sync(0xffffffffu, mt, off));
            float newm = fmaxf(m[i], mt);
            float f = __expf(m[i] - newm);
            float rsum = 0.f;
            #pragma unroll
            for (int j = 0; j < 4; j++) {
                float p = __expf(s[i][j] - newm);
                s[i][j] = p;
                rsum += p;
            }
            #pragma unroll
            for (int off = 8; off >= 1; off >>= 1)
                rsum += __shfl_xor_sync(0xffffffffu, rsum, off);
            l[i] = l[i] * f + rsum;
            m[i] = newm;
            #pragma unroll
            for (int c = 0; c < 8; c++) acc[i][c] *= f;
        }

        // stage P transposed
        #pragma unroll
        for (int i = 0; i < 4; i++)
            #pragma unroll
            for (int j = 0; j < 4; j++)
                Pt[(tx * 4 + j) * PSTR + ty * 4 + i] = s[i][j];
        __syncthreads();

        // O += P V
        #pragma unroll 2
        for (int j = 0; j < 64; j++) {
            float p_[4], v_[8];
            *(float4*)p_ = *(const float4*)&Pt[j * PSTR + ty * 4];
            *(float4*)&v_[0] = *(const float4*)&Vs[j * 128 + tx * 8];
            *(float4*)&v_[4] = *(const float4*)&Vs[j * 128 + tx * 8 + 4];
            #pragma unroll
            for (int i = 0; i < 4; i++)
                #pragma unroll
                for (int c = 0; c < 8; c++)
                    acc[i][c] = fmaf(p_[i], v_[c], acc[i][c]);
        }
    }

    // normalize + write out
    #pragma unroll
    for (int i = 0; i < 4; i++) {
        float inv = 1.0f / l[i];
        size_t off = ((size_t)(bb * SS + q0 + ty * 4 + i) * HH) + hh * HDD + tx * 8;
        *(float4*)(o + off) = make_float4(acc[i][0] * inv, acc[i][1] * inv,
                                          acc[i][2] * inv, acc[i][3] * inv);
        *(float4*)(o + off + 4) = make_float4(acc[i][4] * inv, acc[i][5] * inv,
                                              acc[i][6] * inv, acc[i][7] * inv);
    }
}

// ---------------- launch ----------------------------------------------------
extern "C" void kernel_launch(void* const* d_in, const int* in_sizes, int n_in,
                              void* d_out, int out_size)
{
    const float* x     = (const float*)d_in[0];
    // d_in[1] = mask (causal triu k=1) — applied analytically, not read
    const float* wq    = (const float*)d_in[2];
    const float* wk    = (const float*)d_in[3];
    const float* wv    = (const float*)d_in[4];
    const float* wo    = (const float*)d_in[5];
    const float* w_in  = (const float*)d_in[6];
    const float* w_out = (const float*)d_in[7];
    const float* ln1g  = (const float*)d_in[8];
    const float* ln1b  = (const float*)d_in[9];
    const float* ln2g  = (const float*)d_in[10];
    const float* ln2b  = (const float*)d_in[11];
    float* out = (float*)d_out;

    float *xn, *q, *k, *v, *at, *h, *hn, *ff;
    cudaGetSymbolAddress((void**)&xn, g_xn);
    cudaGetSymbolAddress((void**)&q,  g_q);
    cudaGetSymbolAddress((void**)&k,  g_k);
    cudaGetSymbolAddress((void**)&v,  g_v);
    cudaGetSymbolAddress((void**)&at, g_at);
    cudaGetSymbolAddress((void**)&h,  g_h);
    cudaGetSymbolAddress((void**)&hn, g_hn);
    cudaGetSymbolAddress((void**)&ff, g_ff);

    cudaFuncSetAttribute(flash_kernel,
                         cudaFuncAttributeMaxDynamicSharedMemorySize, FL_SMEM);

    dim3 gP(HH / 128, MTOK / 128);      // proj GEMMs: 16 x 32
    dim3 gF(FFD / 128, MTOK / 128);     // FFN up:     64 x 32

    // 1) LN1
    ln_kernel<<<MTOK, 256>>>(x, ln1g, ln1b, xn);
    // 2) Q,K,V projections
    sgemm<0><<<gP, 256>>>(xn, wq, nullptr, q, MTOK, HH, HH);
    sgemm<0><<<gP, 256>>>(xn, wk, nullptr, k, MTOK, HH, HH);
    sgemm<0><<<gP, 256>>>(xn, wv, nullptr, v, MTOK, HH, HH);
    // 3) causal flash attention
    flash_kernel<<<dim3(SS / 64, BB * NHH), 256, FL_SMEM>>>(q, k, v, at);
    // 4) output proj + residual
    sgemm<1><<<gP, 256>>>(at, wo, x, h, MTOK, HH, HH);
    // 5) LN2
    ln_kernel<<<MTOK, 256>>>(h, ln2g, ln2b, hn);
    // 6) FFN up + GELU
    sgemm<2><<<gF, 256>>>(hn, w_in, nullptr, ff, MTOK, FFD, HH);
    // 7) FFN down + residual
    sgemm<1><<<gP, 256>>>(ff, w_out, h, out, MTOK, HH, FFD);
}